// round 5
// baseline (speedup 1.0000x reference)
#include <cuda_runtime.h>
#include <cuda_fp16.h>
#include <cstdint>

// Problem constants (fixed by setup_inputs)
#define BATCH   8
#define HH      128
#define WW      128
#define CC      256
#define HID     64
#define NTOK    (HH*WW)          // 16384 tokens per batch
#define NP      1024
#define KKEEP   768
#define TOK_ALL (BATCH*NTOK)     // 131072
#define BM      256
#define NTILES  (TOK_ALL/BM)     // 512
#define THREADS 512
#define NSM     148

// Scratch (device globals — no allocation allowed)
__device__ float    g_imp[TOK_ALL];
__device__ unsigned g_key[BATCH*NP];
__device__ unsigned g_ball[BATCH*32];

// ---------------- SMEM layout (bytes) ----------------
// BH/BL: w1 hi/lo, 8x8-tile blocked fp16 (tile idx = k8*8+n8, 128B/tile): 32KB each
// A: 16 warps x 4KB warp-private (hi 2KB + lo 2KB), XOR-swizzled tiles
// EX: fp32 partial exchange, 256 rows x 66-float stride
#define OFF_BH  0
#define OFF_BL  32768
#define OFF_A   65536
#define OFF_EX  131072
#define OFF_B1  198656
#define OFF_W2  198912
#define SMEM_SZ 199168

// ---------------- asm helpers ----------------
static __device__ __forceinline__ uint32_t smem_u32(const void* p) {
    uint32_t a;
    asm("{ .reg .u64 t; cvta.to.shared.u64 t, %1; cvt.u32.u64 %0, t; }" : "=r"(a) : "l"(p));
    return a;
}
static __device__ __forceinline__ uint32_t h2u(__half2 h) {
    return *reinterpret_cast<uint32_t*>(&h);
}
#define LDSM_X4(r, a) \
    asm volatile("ldmatrix.sync.aligned.m8n8.x4.shared.b16 {%0,%1,%2,%3}, [%4];" \
        : "=r"((r)[0]), "=r"((r)[1]), "=r"((r)[2]), "=r"((r)[3]) : "r"(a))
#define LDSM_X4T(r, a) \
    asm volatile("ldmatrix.sync.aligned.m8n8.x4.trans.shared.b16 {%0,%1,%2,%3}, [%4];" \
        : "=r"((r)[0]), "=r"((r)[1]), "=r"((r)[2]), "=r"((r)[3]) : "r"(a))
#define MMA16816(d, a, b) \
    asm volatile("mma.sync.aligned.m16n8k16.row.col.f32.f16.f16.f32 " \
        "{%0,%1,%2,%3}, {%4,%5,%6,%7}, {%8,%9}, {%0,%1,%2,%3};" \
        : "+f"((d)[0]), "+f"((d)[1]), "+f"((d)[2]), "+f"((d)[3]) \
        : "r"((a)[0]), "r"((a)[1]), "r"((a)[2]), "r"((a)[3]), "r"((b)[0]), "r"((b)[1]))
#define STS64(a, r0, r1) \
    asm volatile("st.shared.v2.b32 [%0], {%1,%2};" :: "r"(a), "r"(r0), "r"(r1) : "memory")
#define STS64F(a, f0, f1) \
    asm volatile("st.shared.v2.f32 [%0], {%1,%2};" :: "r"(a), "f"(f0), "f"(f1) : "memory")

static __device__ __forceinline__ float gelu_exact(float v) {
    return 0.5f * v * (1.0f + erff(v * 0.7071067811865476f));
}

// ============ Kernel A: fp16-split HMMA MLP -> per-token importance ============
// H = gelu(X[131072,256] @ W1[256,64] + b1); imp = sigmoid(H @ w2 + b2)
// 3-product fp16 split: Ah.Bh + Ah.Bl + Al.Bh (fp32 accum); err ~1e-7 << score gaps.
// 16 warps in 2 k-groups of 8; warp-private A staging; no block barriers in mainloop.
__global__ __launch_bounds__(THREADS, 1) void score_mma(
    const float* __restrict__ tokens,
    const float* __restrict__ w1,
    const float* __restrict__ b1,
    const float* __restrict__ w2,
    const float* __restrict__ b2)
{
    extern __shared__ char sm[];
    const uint32_t sb = smem_u32(sm);
    const int tid = threadIdx.x;
    const int lane = tid & 31, wid = tid >> 5;
    const int grp = wid >> 3, w2i = wid & 7;
    const int g = lane >> 2, tig = lane & 3;

    if (tid < 64) {
        ((float*)(sm + OFF_B1))[tid] = b1[tid];
        ((float*)(sm + OFF_W2))[tid] = w2[tid];
    }
    const float b2v = b2[0];

    // stage w1 hi/lo once: tile idx (k>>3)*8 + (n>>3), byte (k&7)*16 + (n&7)*2
#pragma unroll
    for (int j = 0; j < 16; ++j) {
        int pi = tid + j * THREADS;
        int k = pi >> 5, n = (pi & 31) * 2;
        float2 v = *(const float2*)(w1 + k * HID + n);
        __half2 h = __floats2half2_rn(v.x, v.y);
        __half2 l = __floats2half2_rn(v.x - __low2float(h), v.y - __high2float(h));
        uint32_t off = (uint32_t)(((k >> 3) * 8 + (n >> 3)) * 128 + (k & 7) * 16 + (n & 7) * 2);
        *(uint32_t*)(sm + OFF_BH + off) = h2u(h);
        *(uint32_t*)(sm + OFF_BL + off) = h2u(l);
    }
    __syncthreads();

    // lane constants
    const int rl4 = lane & 3, f4i = lane >> 2;
    const int ktL = f4i >> 1;                       // A-store k-tile
    const uint32_t kb8 = (uint32_t)(f4i & 1) * 8;   // byte half within tile row
    const uint32_t abase = sb + OFF_A + wid * 4096; // hi; lo at +2048
    const int m_ = lane >> 3;
    const int rtL = m_ & 1, ktL2 = m_ >> 1;         // A-ldsm tile selectors
    const uint32_t slotL = (uint32_t)(lane & 7);
    const uint32_t bconst = (uint32_t)(lane >> 4) * 32768u
                          + (uint32_t)((lane >> 3) & 1) * 1024u + slotL * 16u;

    float acc[2][8][4];
#pragma unroll
    for (int mi = 0; mi < 2; ++mi)
#pragma unroll
        for (int nt = 0; nt < 8; ++nt)
#pragma unroll
            for (int q = 0; q < 4; ++q) acc[mi][nt][q] = 0.0f;

    for (int tile = blockIdx.x; tile < NTILES; tile += gridDim.x) {
        const int R0 = tile * BM + w2i * 32;
        const float4* ap = (const float4*)tokens
                         + ((size_t)(R0 + rl4) * 64 + grp * 32 + f4i);

        for (int c = 0; c < 4; ++c) {
            __syncwarp();
#pragma unroll
            for (int p = 0; p < 8; ++p) {
                float4 v = ap[p * 256 + c * 8];
                __half2 h0 = __floats2half2_rn(v.x, v.y);
                __half2 h1 = __floats2half2_rn(v.z, v.w);
                __half2 l0 = __floats2half2_rn(v.x - __low2float(h0), v.y - __high2float(h0));
                __half2 l1 = __floats2half2_rn(v.z - __low2float(h1), v.w - __high2float(h1));
                int rloc = p * 4 + rl4;
                uint32_t addr = abase
                    + (uint32_t)((((rloc >> 3) * 4 + ktL) << 7)
                    + (((rloc & 7) ^ (ktL << 1)) << 4)) + kb8;
                STS64(addr,        h2u(h0), h2u(h1));
                STS64(addr + 2048, h2u(l0), h2u(l1));
            }
            __syncwarp();

            const int ktg = grp * 16 + c * 4;   // global k8 index base of chunk
#pragma unroll
            for (int st = 0; st < 2; ++st) {
                uint32_t ah[2][4], al[2][4];
#pragma unroll
                for (int mi = 0; mi < 2; ++mi) {
                    int rt = mi * 2 + rtL;
                    int kt = st * 2 + ktL2;
                    uint32_t ad = abase
                        + (uint32_t)(((rt * 4 + kt) << 7) + ((slotL ^ (kt << 1)) << 4));
                    LDSM_X4(ah[mi], ad);
                    LDSM_X4(al[mi], ad + 2048);
                }
                uint32_t baddr = sb + OFF_BH + bconst + (uint32_t)((ktg + st * 2) * 1024);
#pragma unroll
                for (int nt = 0; nt < 8; ++nt) {
                    uint32_t b4[4];
                    LDSM_X4T(b4, baddr + nt * 128);
#pragma unroll
                    for (int mi = 0; mi < 2; ++mi) {
                        MMA16816(acc[mi][nt], ah[mi], b4);      // hi*hi
                        MMA16816(acc[mi][nt], ah[mi], b4 + 2);  // hi*lo
                        MMA16816(acc[mi][nt], al[mi], b4);      // lo*hi
                    }
                }
            }
        }

        // ---- cross-group partial exchange: group stores mi=grp^1, computes mi=grp ----
        {
            const int miS = grp ^ 1;
            const int er0 = w2i * 32 + miS * 16 + g;
#pragma unroll
            for (int nt = 0; nt < 8; ++nt) {
                uint32_t a0 = sb + OFF_EX + (uint32_t)(((er0)     * 66 + nt * 8 + tig * 2) * 4);
                uint32_t a1 = sb + OFF_EX + (uint32_t)(((er0 + 8) * 66 + nt * 8 + tig * 2) * 4);
                STS64F(a0, acc[miS][nt][0], acc[miS][nt][1]);
                STS64F(a1, acc[miS][nt][2], acc[miS][nt][3]);
            }
        }
        __syncthreads();
        {
            const int miE = grp;
            const float* b1s = (const float*)(sm + OFF_B1);
            const float* w2s = (const float*)(sm + OFF_W2);
            const int er0 = w2i * 32 + miE * 16 + g;
            float p0 = 0.0f, p1 = 0.0f;
#pragma unroll
            for (int nt = 0; nt < 8; ++nt) {
                float2 e0 = *(const float2*)(sm + OFF_EX + ((er0)     * 66 + nt * 8 + tig * 2) * 4);
                float2 e1 = *(const float2*)(sm + OFF_EX + ((er0 + 8) * 66 + nt * 8 + tig * 2) * 4);
                int c0 = nt * 8 + tig * 2, c1 = c0 + 1;
                float bb0 = b1s[c0], bb1 = b1s[c1];
                float ww0 = w2s[c0], ww1 = w2s[c1];
                p0 += gelu_exact(acc[miE][nt][0] + e0.x + bb0) * ww0
                    + gelu_exact(acc[miE][nt][1] + e0.y + bb1) * ww1;
                p1 += gelu_exact(acc[miE][nt][2] + e1.x + bb0) * ww0
                    + gelu_exact(acc[miE][nt][3] + e1.y + bb1) * ww1;
            }
            p0 += __shfl_xor_sync(0xffffffffu, p0, 1);
            p0 += __shfl_xor_sync(0xffffffffu, p0, 2);
            p1 += __shfl_xor_sync(0xffffffffu, p1, 1);
            p1 += __shfl_xor_sync(0xffffffffu, p1, 2);
            if (tig == 0) {
                int r = tile * BM + w2i * 32 + miE * 16 + g;
                g_imp[r]     = 1.0f / (1.0f + expf(-(p0 + b2v)));
                g_imp[r + 8] = 1.0f / (1.0f + expf(-(p1 + b2v)));
            }
#pragma unroll
            for (int mi = 0; mi < 2; ++mi)
#pragma unroll
                for (int nt = 0; nt < 8; ++nt)
#pragma unroll
                    for (int q = 0; q < 4; ++q) acc[mi][nt][q] = 0.0f;
        }
        __syncthreads();   // EX reads done before next tile's stores
    }
}

// ============ Kernel B1: patch scores -> ordered-uint keys ============
__global__ __launch_bounds__(256) void pscore_kernel()
{
    const int pg = blockIdx.x * 256 + threadIdx.x;   // 8192 patches
    const int b = pg >> 10, p = pg & (NP - 1);
    const int pr = p >> 5, pc = p & 31;
    const float* base = g_imp + b * NTOK;
    float sum = 0.0f;
#pragma unroll
    for (int i = 0; i < 4; i++) {
        float4 v = *(const float4*)(base + (pr * 4 + i) * WW + pc * 4);
        sum += (v.x + v.y) + (v.z + v.w);
    }
    g_key[pg] = __float_as_uint(sum);   // sums of sigmoids > 0: uint order == float order
}

// ============ Kernel B2: stable top-768 rank -> keep ballots ============
__global__ __launch_bounds__(128) void rank_kernel()
{
    __shared__ unsigned sk[NP];
    const int b = blockIdx.x >> 3;
    const int tid = threadIdx.x;
    const int p = (blockIdx.x & 7) * 128 + tid;

#pragma unroll
    for (int i = 0; i < 8; ++i)
        sk[tid + i * 128] = g_key[b * NP + tid + i * 128];
    __syncthreads();

    const unsigned kp = sk[p];
    int rank = 0;
    const uint4* s4 = (const uint4*)sk;
#pragma unroll 4
    for (int j4 = 0; j4 < NP / 4; ++j4) {
        uint4 v = s4[j4];
        int j = j4 * 4;
        rank += (int)((v.x > kp) || (v.x == kp && (j + 0) < p));
        rank += (int)((v.y > kp) || (v.y == kp && (j + 1) < p));
        rank += (int)((v.z > kp) || (v.z == kp && (j + 2) < p));
        rank += (int)((v.w > kp) || (v.w == kp && (j + 3) < p));
    }
    const unsigned mask = __ballot_sync(0xffffffffu, rank < KKEEP);
    if ((tid & 31) == 0)
        g_ball[b * 32 + (p >> 5)] = mask;
}

// ============ Kernel C: ballot-decode + gather + spatial reassembly ============
__global__ __launch_bounds__(128) void gather_kernel(
    const float* __restrict__ tokens, float* __restrict__ out)
{
    const int k = blockIdx.x;            // kept slot 0..767
    const int b = blockIdx.y;
    __shared__ int s_p;

    if (threadIdx.x < 32) {
        const int w = threadIdx.x;
        unsigned bal = g_ball[b * 32 + w];
        int cnt = __popc(bal);
        int pre = cnt;
#pragma unroll
        for (int d = 1; d < 32; d <<= 1) {
            int t = __shfl_up_sync(0xffffffffu, pre, d);
            if (w >= d) pre += t;
        }
        pre -= cnt;                      // exclusive prefix of kept count
        if (k >= pre && k < pre + cnt) {
            int bit = __fns(bal, 0, (k - pre) + 1);
            s_p = w * 32 + bit;
        }
    }
    __syncthreads();
    const int p = s_p;
    const int pr = p >> 5, pc = p & 31;
    const int kr = k >> 5, kc = k & 31;

    const float4* src = (const float4*)(tokens + (size_t)b * NTOK * CC);
    float4*       dst = (float4*)(out + (size_t)b * (KKEEP * 16) * CC);
    const int t = threadIdx.x;

#pragma unroll
    for (int i = 0; i < 4; i++) {
        size_t so   = (size_t)((pr * 4 + i) * WW + pc * 4) * (CC / 4);
        size_t dofs = (size_t)((kr * 4 + i) * WW + kc * 4) * (CC / 4);
#pragma unroll
        for (int it = 0; it < 2; it++) {
            int e = it * 128 + t;
            dst[dofs + e] = src[so + e];
        }
    }
}

// ============================ launch ============================
extern "C" void kernel_launch(void* const* d_in, const int* in_sizes, int n_in,
                              void* d_out, int out_size)
{
    const float* tokens = (const float*)d_in[0];
    const float* w1 = (const float*)d_in[1];
    const float* b1 = (const float*)d_in[2];
    const float* w2 = (const float*)d_in[3];
    const float* b2 = (const float*)d_in[4];
    (void)in_sizes; (void)n_in; (void)out_size;

    cudaFuncSetAttribute(score_mma, cudaFuncAttributeMaxDynamicSharedMemorySize, SMEM_SZ);
    score_mma<<<NSM, THREADS, SMEM_SZ>>>(tokens, w1, b1, w2, b2);
    pscore_kernel<<<BATCH * NP / 256, 256>>>();
    rank_kernel<<<64, 128>>>();
    gather_kernel<<<dim3(KKEEP, BATCH), 128>>>(tokens, (float*)d_out);
}

// round 6
// speedup vs baseline: 1.1837x; 1.1837x over previous
#include <cuda_runtime.h>
#include <cuda_fp16.h>
#include <cstdint>

// Problem constants (fixed by setup_inputs)
#define BATCH   8
#define HH      128
#define WW      128
#define CC      256
#define HID     64
#define NTOK    (HH*WW)          // 16384 tokens per batch
#define NP      1024
#define KKEEP   768
#define TOK_ALL (BATCH*NTOK)     // 131072
#define BM      256
#define NBLK    (TOK_ALL/BM)     // 512

// Scratch (device globals — no allocation allowed)
__device__ float g_imp[TOK_ALL];
__device__ int   g_idx[BATCH*KKEEP];

// ---------------- SMEM layout (bytes) ----------------
// BH/BL: w1 hi/lo, 8x8-tile blocked fp16 (tile idx = k8*8+n8, 128B/tile): 32KB each.
// BL must sit at BH+32768 (fused hi/lo LDSM addressing via lane>>4).
#define OFF_BH  0
#define OFF_BL  32768
#define OFF_B1  65536
#define OFF_W2  65792
#define SMEM_SZ 66048

// ---------------- asm helpers ----------------
static __device__ __forceinline__ uint32_t smem_u32(const void* p) {
    uint32_t a;
    asm("{ .reg .u64 t; cvta.to.shared.u64 t, %1; cvt.u32.u64 %0, t; }" : "=r"(a) : "l"(p));
    return a;
}
static __device__ __forceinline__ uint32_t h2u(__half2 h) {
    return *reinterpret_cast<uint32_t*>(&h);
}
#define LDSM_X4T(r, a) \
    asm volatile("ldmatrix.sync.aligned.m8n8.x4.trans.shared.b16 {%0,%1,%2,%3}, [%4];" \
        : "=r"((r)[0]), "=r"((r)[1]), "=r"((r)[2]), "=r"((r)[3]) : "r"(a))
#define MMA16816(d, a, b) \
    asm volatile("mma.sync.aligned.m16n8k16.row.col.f32.f16.f16.f32 " \
        "{%0,%1,%2,%3}, {%4,%5,%6,%7}, {%8,%9}, {%0,%1,%2,%3};" \
        : "+f"((d)[0]), "+f"((d)[1]), "+f"((d)[2]), "+f"((d)[3]) \
        : "r"((a)[0]), "r"((a)[1]), "r"((a)[2]), "r"((a)[3]), "r"((b)[0]), "r"((b)[1]))

static __device__ __forceinline__ float gelu_exact(float v) {
    return 0.5f * v * (1.0f + erff(v * 0.7071067811865476f));
}

// split one float2 into hi/lo fp16x2 register pair
static __device__ __forceinline__ void split_f2(float2 v, uint32_t& hi, uint32_t& lo) {
    __half2 h = __floats2half2_rn(v.x, v.y);
    float2 hf = __half22float2(h);
    __half2 l = __floats2half2_rn(v.x - hf.x, v.y - hf.y);
    hi = h2u(h); lo = h2u(l);
}

// ============ Kernel A: fp16-split HMMA MLP -> per-token importance ============
// H = gelu(X[131072,256] @ W1[256,64] + b1); imp = sigmoid(H @ w2 + b2)
// 3-product fp16 split: Ah.Bh + Ah.Bl + Al.Bh (fp32 accum); err ~1e-7 << score gaps.
// A fragments loaded DIRECTLY from gmem (no smem round trip, no mainloop barriers).
__global__ __launch_bounds__(256, 2) void score_mma(
    const float* __restrict__ tokens,
    const float* __restrict__ w1,
    const float* __restrict__ b1,
    const float* __restrict__ w2,
    const float* __restrict__ b2)
{
    extern __shared__ char sm[];
    const uint32_t sb = smem_u32(sm);
    const int tid = threadIdx.x;
    const int lane = tid & 31, wid = tid >> 5;      // 8 warps
    const int g = lane >> 2, tig = lane & 3;

    if (tid < 64) {
        ((float*)(sm + OFF_B1))[tid] = b1[tid];
        ((float*)(sm + OFF_W2))[tid] = w2[tid];
    }
    const float b2v = b2[0];

    // stage w1 hi/lo once: tile idx (k>>3)*8 + (n>>3), byte (k&7)*16 + (n&7)*2
#pragma unroll
    for (int j = 0; j < 32; ++j) {
        int pi = tid + j * 256;                     // 8192 half2 pairs
        int k = pi >> 5, n = (pi & 31) * 2;
        float2 v = *(const float2*)(w1 + k * HID + n);
        uint32_t hb, lb;
        split_f2(v, hb, lb);
        uint32_t off = (uint32_t)(((k >> 3) * 8 + (n >> 3)) * 128 + (k & 7) * 16 + (n & 7) * 2);
        *(uint32_t*)(sm + OFF_BH + off) = hb;
        *(uint32_t*)(sm + OFF_BL + off) = lb;
    }
    __syncthreads();    // the ONLY block barrier; B is read-only hereafter

    // B fused hi/lo ldmatrix base (R3-proven): lanes 16-31 fetch the BL copies
    const uint32_t b_base = sb + OFF_BH + (uint32_t)(lane >> 4) * 32768u
                          + (uint32_t)((lane >> 3) & 1) * 1024u
                          + (uint32_t)(lane & 7) * 16u;

    // A fragment gmem base: warp rows [bid*256 + wid*32, +32)
    const float* a0 = tokens + (size_t)(blockIdx.x * BM + wid * 32 + g) * CC + tig * 2;

    float acc[2][8][4];
#pragma unroll
    for (int mi = 0; mi < 2; ++mi)
#pragma unroll
        for (int nt = 0; nt < 8; ++nt)
#pragma unroll
            for (int q = 0; q < 4; ++q) acc[mi][nt][q] = 0.0f;

    for (int c = 0; c < 8; ++c) {                   // k32 chunks
#pragma unroll
        for (int kt = 0; kt < 2; ++kt) {            // k16 steps
            // direct-LDG A fragments for both mi (8 independent LDG.64)
            float2 f[2][4];
#pragma unroll
            for (int mi = 0; mi < 2; ++mi) {
                const float* base = a0 + (size_t)(mi * 16) * CC + c * 32 + kt * 16;
                f[mi][0] = *(const float2*)(base);
                f[mi][1] = *(const float2*)(base + 8 * CC);
                f[mi][2] = *(const float2*)(base + 8);
                f[mi][3] = *(const float2*)(base + 8 * CC + 8);
            }
            uint32_t ah[2][4], al[2][4];
#pragma unroll
            for (int mi = 0; mi < 2; ++mi)
#pragma unroll
                for (int q = 0; q < 4; ++q)
                    split_f2(f[mi][q], ah[mi][q], al[mi][q]);

            const int ktg = c * 4 + kt * 2;         // global k8 index
#pragma unroll
            for (int nt = 0; nt < 8; ++nt) {
                uint32_t b4[4];                     // {bh0,bh1,bl0,bl1}
                LDSM_X4T(b4, b_base + (uint32_t)((ktg * 8 + nt) * 128));
#pragma unroll
                for (int mi = 0; mi < 2; ++mi) {
                    MMA16816(acc[mi][nt], ah[mi], b4);      // hi*hi
                    MMA16816(acc[mi][nt], ah[mi], b4 + 2);  // hi*lo
                    MMA16816(acc[mi][nt], al[mi], b4);      // lo*hi
                }
            }
        }
    }

    // ---- epilogue: gelu(h+b1)*w2, reduce 64 cols, sigmoid (R3-proven) ----
    const float* b1s = (const float*)(sm + OFF_B1);
    const float* w2s = (const float*)(sm + OFF_W2);
#pragma unroll
    for (int mi = 0; mi < 2; ++mi) {
        float p0 = 0.0f, p1 = 0.0f;
#pragma unroll
        for (int nt = 0; nt < 8; ++nt) {
            int c0 = nt * 8 + tig * 2, c1 = c0 + 1;
            float bb0 = b1s[c0], bb1 = b1s[c1];
            float ww0 = w2s[c0], ww1 = w2s[c1];
            p0 += gelu_exact(acc[mi][nt][0] + bb0) * ww0
                + gelu_exact(acc[mi][nt][1] + bb1) * ww1;
            p1 += gelu_exact(acc[mi][nt][2] + bb0) * ww0
                + gelu_exact(acc[mi][nt][3] + bb1) * ww1;
        }
        p0 += __shfl_xor_sync(0xffffffffu, p0, 1);
        p0 += __shfl_xor_sync(0xffffffffu, p0, 2);
        p1 += __shfl_xor_sync(0xffffffffu, p1, 1);
        p1 += __shfl_xor_sync(0xffffffffu, p1, 2);
        if (tig == 0) {
            int r0 = blockIdx.x * BM + wid * 32 + mi * 16 + g;
            g_imp[r0]     = 1.0f / (1.0f + expf(-(p0 + b2v)));
            g_imp[r0 + 8] = 1.0f / (1.0f + expf(-(p1 + b2v)));
        }
    }
}

// ============ Kernel B: patch scores + stable top-768 (R1-proven) ============
__global__ __launch_bounds__(1024) void select_kernel()
{
    const int b = blockIdx.x;
    const int p = threadIdx.x;
    __shared__ float s[NP];
    __shared__ int   woff[32];

    const int pr = p >> 5, pc = p & 31;
    const float* base = g_imp + b * NTOK;
    float sum = 0.0f;
#pragma unroll
    for (int i = 0; i < 4; i++) {
        float4 v = *(const float4*)(base + (pr * 4 + i) * WW + pc * 4);
        sum += (v.x + v.y) + (v.z + v.w);
    }
    s[p] = sum;                          // sum monotone in mean; ranking identical
    __syncthreads();

    const float sp = sum;
    int rank = 0;
    const float4* s4 = (const float4*)s;
#pragma unroll 4
    for (int j4 = 0; j4 < NP / 4; j4++) {
        float4 v = s4[j4];
        int j = j4 * 4;
        rank += (int)((v.x > sp) || (v.x == sp && (j + 0) < p));
        rank += (int)((v.y > sp) || (v.y == sp && (j + 1) < p));
        rank += (int)((v.z > sp) || (v.z == sp && (j + 2) < p));
        rank += (int)((v.w > sp) || (v.w == sp && (j + 3) < p));
    }
    const bool kept = (rank < KKEEP);

    const unsigned mask = __ballot_sync(0xffffffffu, kept);
    const int lane = p & 31, warp = p >> 5;
    const int lpre = __popc(mask & ((1u << lane) - 1u));
    if (lane == 0) woff[warp] = __popc(mask);
    __syncthreads();
    if (p < 32) {
        int v = woff[p];
        int inc = v;
        for (int d = 1; d < 32; d <<= 1) {
            int t = __shfl_up_sync(0xffffffffu, inc, d);
            if (lane >= d) inc += t;
        }
        woff[p] = inc - v;
    }
    __syncthreads();
    if (kept)
        g_idx[b * KKEEP + woff[warp] + lpre] = p;
}

// ============ Kernel C: gather + spatial reassembly (near memory floor) ============
__global__ __launch_bounds__(128) void gather_kernel(
    const float* __restrict__ tokens, float* __restrict__ out)
{
    const int k = blockIdx.x;            // kept slot 0..767
    const int b = blockIdx.y;
    const int p = g_idx[b * KKEEP + k];
    const int pr = p >> 5, pc = p & 31;
    const int kr = k >> 5, kc = k & 31;

    const float4* src = (const float4*)(tokens + (size_t)b * NTOK * CC);
    float4*       dst = (float4*)(out + (size_t)b * (KKEEP * 16) * CC);
    const int t = threadIdx.x;

#pragma unroll
    for (int i = 0; i < 4; i++) {
        size_t so   = (size_t)((pr * 4 + i) * WW + pc * 4) * (CC / 4);
        size_t dofs = (size_t)((kr * 4 + i) * WW + kc * 4) * (CC / 4);
#pragma unroll
        for (int it = 0; it < 2; it++) {
            int e = it * 128 + t;
            dst[dofs + e] = src[so + e];
        }
    }
}

// ============================ launch ============================
extern "C" void kernel_launch(void* const* d_in, const int* in_sizes, int n_in,
                              void* d_out, int out_size)
{
    const float* tokens = (const float*)d_in[0];
    const float* w1 = (const float*)d_in[1];
    const float* b1 = (const float*)d_in[2];
    const float* w2 = (const float*)d_in[3];
    const float* b2 = (const float*)d_in[4];
    (void)in_sizes; (void)n_in; (void)out_size;

    cudaFuncSetAttribute(score_mma, cudaFuncAttributeMaxDynamicSharedMemorySize, SMEM_SZ);
    score_mma<<<NBLK, 256, SMEM_SZ>>>(tokens, w1, b1, w2, b2);
    select_kernel<<<BATCH, 1024>>>();
    gather_kernel<<<dim3(KKEEP, BATCH), 128>>>(tokens, (float*)d_out);
}

// round 7
// speedup vs baseline: 1.6078x; 1.3583x over previous
#include <cuda_runtime.h>
#include <cuda_fp16.h>
#include <cstdint>

// Problem constants (fixed by setup_inputs)
#define BATCH   8
#define HH      128
#define WW      128
#define CC      256
#define HID     64
#define NTOK    (HH*WW)          // 16384 tokens per batch
#define NP      1024
#define KKEEP   768
#define TOK_ALL (BATCH*NTOK)     // 131072
#define BM      256
#define NBLK    (TOK_ALL/BM)     // 512

// Scratch (device globals — no allocation allowed)
__device__ float    g_imp[TOK_ALL];
__device__ unsigned g_key[BATCH*NP];
__device__ unsigned g_ball[BATCH*32];

// ---------------- SMEM layout (bytes) ----------------
// BH/BL: w1 hi/lo, 8x8-tile blocked fp16 (tile idx = k8*8+n8, 128B/tile): 32KB each.
// BL must sit at BH+32768 (fused hi/lo LDSM addressing via lane>>4).
#define OFF_BH  0
#define OFF_BL  32768
#define OFF_B1  65536
#define OFF_W2  65792
#define SMEM_SZ 66048

// ---------------- asm helpers ----------------
static __device__ __forceinline__ uint32_t smem_u32(const void* p) {
    uint32_t a;
    asm("{ .reg .u64 t; cvta.to.shared.u64 t, %1; cvt.u32.u64 %0, t; }" : "=r"(a) : "l"(p));
    return a;
}
static __device__ __forceinline__ uint32_t h2u(__half2 h) {
    return *reinterpret_cast<uint32_t*>(&h);
}
#define LDSM_X4T(r, a) \
    asm volatile("ldmatrix.sync.aligned.m8n8.x4.trans.shared.b16 {%0,%1,%2,%3}, [%4];" \
        : "=r"((r)[0]), "=r"((r)[1]), "=r"((r)[2]), "=r"((r)[3]) : "r"(a))
#define MMA16816(d, a, b) \
    asm volatile("mma.sync.aligned.m16n8k16.row.col.f32.f16.f16.f32 " \
        "{%0,%1,%2,%3}, {%4,%5,%6,%7}, {%8,%9}, {%0,%1,%2,%3};" \
        : "+f"((d)[0]), "+f"((d)[1]), "+f"((d)[2]), "+f"((d)[3]) \
        : "r"((a)[0]), "r"((a)[1]), "r"((a)[2]), "r"((a)[3]), "r"((b)[0]), "r"((b)[1]))

static __device__ __forceinline__ float gelu_exact(float v) {
    return 0.5f * v * (1.0f + erff(v * 0.7071067811865476f));
}

// split one float2 into hi/lo fp16x2 register pair
static __device__ __forceinline__ void split_f2(float2 v, uint32_t& hi, uint32_t& lo) {
    __half2 h = __floats2half2_rn(v.x, v.y);
    float2 hf = __half22float2(h);
    __half2 l = __floats2half2_rn(v.x - hf.x, v.y - hf.y);
    hi = h2u(h); lo = h2u(l);
}

// load the 8 A-fragment float2s for one k16 step (direct from gmem; R6-proven map)
static __device__ __forceinline__ void lda(const float* a0, int step, float2 f[2][4]) {
#pragma unroll
    for (int mi = 0; mi < 2; ++mi) {
        const float* base = a0 + (size_t)(mi * 16) * CC + step * 16;
        f[mi][0] = *(const float2*)(base);
        f[mi][1] = *(const float2*)(base + 8 * CC);
        f[mi][2] = *(const float2*)(base + 8);
        f[mi][3] = *(const float2*)(base + 8 * CC + 8);
    }
}

// one k16 step: LDSM all-nt B, split A, product-major MMA stream
static __device__ __forceinline__ void do_step(
    uint32_t b_base, int step, float2 f[2][4], float acc[2][8][4])
{
    uint32_t b4[8][4];                                  // {bh0,bh1,bl0,bl1} per nt
#pragma unroll
    for (int nt = 0; nt < 8; ++nt)
        LDSM_X4T(b4[nt], b_base + (uint32_t)((step * 16 + nt) * 128));

    uint32_t ah[2][4], al[2][4];
#pragma unroll
    for (int mi = 0; mi < 2; ++mi)
#pragma unroll
        for (int q = 0; q < 4; ++q)
            split_f2(f[mi][q], ah[mi][q], al[mi][q]);

    // product-major: same-acc reuse distance = 16 MMAs
#pragma unroll
    for (int nt = 0; nt < 8; ++nt)
#pragma unroll
        for (int mi = 0; mi < 2; ++mi)
            MMA16816(acc[mi][nt], ah[mi], b4[nt]);      // hi*hi
#pragma unroll
    for (int nt = 0; nt < 8; ++nt)
#pragma unroll
        for (int mi = 0; mi < 2; ++mi)
            MMA16816(acc[mi][nt], ah[mi], b4[nt] + 2);  // hi*lo
#pragma unroll
    for (int nt = 0; nt < 8; ++nt)
#pragma unroll
        for (int mi = 0; mi < 2; ++mi)
            MMA16816(acc[mi][nt], al[mi], b4[nt]);      // lo*hi
}

// ============ Kernel A: fp16-split HMMA MLP -> per-token importance ============
// H = gelu(X[131072,256] @ W1[256,64] + b1); imp = sigmoid(H @ w2 + b2)
// 3-product fp16 split (err ~1e-7 << score order-stat gaps); A direct-LDG with
// 1-step register double-buffer; B staged hi/lo in smem once.
__global__ __launch_bounds__(256) void score_mma(
    const float* __restrict__ tokens,
    const float* __restrict__ w1,
    const float* __restrict__ b1,
    const float* __restrict__ w2,
    const float* __restrict__ b2)
{
    extern __shared__ char sm[];
    const uint32_t sb = smem_u32(sm);
    const int tid = threadIdx.x;
    const int lane = tid & 31, wid = tid >> 5;      // 8 warps
    const int g = lane >> 2, tig = lane & 3;

    if (tid < 64) {
        ((float*)(sm + OFF_B1))[tid] = b1[tid];
        ((float*)(sm + OFF_W2))[tid] = w2[tid];
    }
    const float b2v = b2[0];

    // stage w1 hi/lo once: tile idx (k>>3)*8 + (n>>3), byte (k&7)*16 + (n&7)*2
#pragma unroll
    for (int j = 0; j < 32; ++j) {
        int pi = tid + j * 256;                     // 8192 half2 pairs
        int k = pi >> 5, n = (pi & 31) * 2;
        float2 v = *(const float2*)(w1 + k * HID + n);
        uint32_t hb, lb;
        split_f2(v, hb, lb);
        uint32_t off = (uint32_t)(((k >> 3) * 8 + (n >> 3)) * 128 + (k & 7) * 16 + (n & 7) * 2);
        *(uint32_t*)(sm + OFF_BH + off) = hb;
        *(uint32_t*)(sm + OFF_BL + off) = lb;
    }
    __syncthreads();    // the ONLY block barrier; B is read-only hereafter

    // B fused hi/lo ldmatrix base (R3-proven): lanes 16-31 fetch the BL copies
    const uint32_t b_base = sb + OFF_BH + (uint32_t)(lane >> 4) * 32768u
                          + (uint32_t)((lane >> 3) & 1) * 1024u
                          + (uint32_t)(lane & 7) * 16u;

    // A fragment gmem base: warp rows [bid*256 + wid*32, +32)
    const float* a0 = tokens + (size_t)(blockIdx.x * BM + wid * 32 + g) * CC + tig * 2;

    float acc[2][8][4];
#pragma unroll
    for (int mi = 0; mi < 2; ++mi)
#pragma unroll
        for (int nt = 0; nt < 8; ++nt)
#pragma unroll
            for (int q = 0; q < 4; ++q) acc[mi][nt][q] = 0.0f;

    float2 fa[2][4], fb[2][4];
    lda(a0, 0, fa);
    for (int c = 0; c < 8; ++c) {          // 2 k16 steps per iteration
        const int s0 = 2 * c;
        lda(a0, s0 + 1, fb);               // prefetch odd step
        do_step(b_base, s0, fa, acc);
        if (c < 7) lda(a0, s0 + 2, fa);    // prefetch next even step
        do_step(b_base, s0 + 1, fb, acc);
    }

    // ---- epilogue: gelu(h+b1)*w2, reduce 64 cols, sigmoid (R3-proven) ----
    const float* b1s = (const float*)(sm + OFF_B1);
    const float* w2s = (const float*)(sm + OFF_W2);
#pragma unroll
    for (int mi = 0; mi < 2; ++mi) {
        float p0 = 0.0f, p1 = 0.0f;
#pragma unroll
        for (int nt = 0; nt < 8; ++nt) {
            int c0 = nt * 8 + tig * 2, c1 = c0 + 1;
            float bb0 = b1s[c0], bb1 = b1s[c1];
            float ww0 = w2s[c0], ww1 = w2s[c1];
            p0 += gelu_exact(acc[mi][nt][0] + bb0) * ww0
                + gelu_exact(acc[mi][nt][1] + bb1) * ww1;
            p1 += gelu_exact(acc[mi][nt][2] + bb0) * ww0
                + gelu_exact(acc[mi][nt][3] + bb1) * ww1;
        }
        p0 += __shfl_xor_sync(0xffffffffu, p0, 1);
        p0 += __shfl_xor_sync(0xffffffffu, p0, 2);
        p1 += __shfl_xor_sync(0xffffffffu, p1, 1);
        p1 += __shfl_xor_sync(0xffffffffu, p1, 2);
        if (tig == 0) {
            int r0 = blockIdx.x * BM + wid * 32 + mi * 16 + g;
            g_imp[r0]     = 1.0f / (1.0f + expf(-(p0 + b2v)));
            g_imp[r0 + 8] = 1.0f / (1.0f + expf(-(p1 + b2v)));
        }
    }
}

// ============ Kernel B1: patch scores -> ordered-uint keys (R5-proven) ============
__global__ __launch_bounds__(256) void pscore_kernel()
{
    const int pg = blockIdx.x * 256 + threadIdx.x;   // 8192 patches
    const int b = pg >> 10, p = pg & (NP - 1);
    const int pr = p >> 5, pc = p & 31;
    const float* base = g_imp + b * NTOK;
    float sum = 0.0f;
#pragma unroll
    for (int i = 0; i < 4; i++) {
        float4 v = *(const float4*)(base + (pr * 4 + i) * WW + pc * 4);
        sum += (v.x + v.y) + (v.z + v.w);
    }
    g_key[pg] = __float_as_uint(sum);   // sums of sigmoids > 0: uint order == float order
}

// ============ Kernel B2: stable top-768 rank -> keep ballots (R5-proven) ============
__global__ __launch_bounds__(128) void rank_kernel()
{
    __shared__ unsigned sk[NP];
    const int b = blockIdx.x >> 3;
    const int tid = threadIdx.x;
    const int p = (blockIdx.x & 7) * 128 + tid;

#pragma unroll
    for (int i = 0; i < 8; ++i)
        sk[tid + i * 128] = g_key[b * NP + tid + i * 128];
    __syncthreads();

    const unsigned kp = sk[p];
    int rank = 0;
    const uint4* s4 = (const uint4*)sk;
#pragma unroll 4
    for (int j4 = 0; j4 < NP / 4; ++j4) {
        uint4 v = s4[j4];
        int j = j4 * 4;
        rank += (int)((v.x > kp) || (v.x == kp && (j + 0) < p));
        rank += (int)((v.y > kp) || (v.y == kp && (j + 1) < p));
        rank += (int)((v.z > kp) || (v.z == kp && (j + 2) < p));
        rank += (int)((v.w > kp) || (v.w == kp && (j + 3) < p));
    }
    const unsigned mask = __ballot_sync(0xffffffffu, rank < KKEEP);
    if ((tid & 31) == 0)
        g_ball[b * 32 + (p >> 5)] = mask;
}

// ============ Kernel C: ballot-decode + gather + spatial reassembly (R5-proven) ============
__global__ __launch_bounds__(128) void gather_kernel(
    const float* __restrict__ tokens, float* __restrict__ out)
{
    const int k = blockIdx.x;            // kept slot 0..767
    const int b = blockIdx.y;
    __shared__ int s_p;

    if (threadIdx.x < 32) {
        const int w = threadIdx.x;
        unsigned bal = g_ball[b * 32 + w];
        int cnt = __popc(bal);
        int pre = cnt;
#pragma unroll
        for (int d = 1; d < 32; d <<= 1) {
            int t = __shfl_up_sync(0xffffffffu, pre, d);
            if (w >= d) pre += t;
        }
        pre -= cnt;                      // exclusive prefix of kept count
        if (k >= pre && k < pre + cnt) {
            int bit = __fns(bal, 0, (k - pre) + 1);
            s_p = w * 32 + bit;
        }
    }
    __syncthreads();
    const int p = s_p;
    const int pr = p >> 5, pc = p & 31;
    const int kr = k >> 5, kc = k & 31;

    const float4* src = (const float4*)(tokens + (size_t)b * NTOK * CC);
    float4*       dst = (float4*)(out + (size_t)b * (KKEEP * 16) * CC);
    const int t = threadIdx.x;

#pragma unroll
    for (int i = 0; i < 4; i++) {
        size_t so   = (size_t)((pr * 4 + i) * WW + pc * 4) * (CC / 4);
        size_t dofs = (size_t)((kr * 4 + i) * WW + kc * 4) * (CC / 4);
#pragma unroll
        for (int it = 0; it < 2; it++) {
            int e = it * 128 + t;
            dst[dofs + e] = src[so + e];
        }
    }
}

// ============================ launch ============================
extern "C" void kernel_launch(void* const* d_in, const int* in_sizes, int n_in,
                              void* d_out, int out_size)
{
    const float* tokens = (const float*)d_in[0];
    const float* w1 = (const float*)d_in[1];
    const float* b1 = (const float*)d_in[2];
    const float* w2 = (const float*)d_in[3];
    const float* b2 = (const float*)d_in[4];
    (void)in_sizes; (void)n_in; (void)out_size;

    cudaFuncSetAttribute(score_mma, cudaFuncAttributeMaxDynamicSharedMemorySize, SMEM_SZ);
    score_mma<<<NBLK, 256, SMEM_SZ>>>(tokens, w1, b1, w2, b2);
    pscore_kernel<<<BATCH * NP / 256, 256>>>();
    rank_kernel<<<64, 128>>>();
    gather_kernel<<<dim3(KKEEP, BATCH), 128>>>(tokens, (float*)d_out);
}